// round 1
// baseline (speedup 1.0000x reference)
#include <cuda_runtime.h>
#include <cuda_bf16.h>

#define FEATS 64
#define MAX_NODES 100000

// Scratch (alloc-free rule: __device__ globals)
__device__ float g_sum[(size_t)MAX_NODES * FEATS];
__device__ float g_deg[MAX_NODES];

// ---------------------------------------------------------------------------
// Kernel 1: zero the accumulators
// ---------------------------------------------------------------------------
__global__ void zero_kernel(int n_nodes) {
    int stride = gridDim.x * blockDim.x;
    int i = blockIdx.x * blockDim.x + threadIdx.x;
    int total4 = n_nodes * (FEATS / 4);
    float4 z = make_float4(0.f, 0.f, 0.f, 0.f);
    float4* s4 = reinterpret_cast<float4*>(g_sum);
    for (int idx = i; idx < total4; idx += stride) s4[idx] = z;
    for (int idx = i; idx < n_nodes; idx += stride) g_deg[idx] = 0.f;
}

// ---------------------------------------------------------------------------
// Kernel 2: edge scatter. Half-warp (16 lanes) per edge; float4 vector atomics.
// ---------------------------------------------------------------------------
__global__ void scatter_kernel(const float* __restrict__ x,
                               const int* __restrict__ src,
                               const int* __restrict__ dst,
                               int n_edges) {
    int e    = blockIdx.x * (blockDim.x >> 4) + (threadIdx.x >> 4);
    int lane = threadIdx.x & 15;
    if (e >= n_edges) return;
    int s = __ldg(&src[e]);
    int d = __ldg(&dst[e]);
    const float4* xrow = reinterpret_cast<const float4*>(x + (size_t)s * FEATS);
    float4 v = __ldg(&xrow[lane]);
    float4* srow = reinterpret_cast<float4*>(g_sum + (size_t)d * FEATS);
    atomicAdd(&srow[lane], v);   // sm_90+: RED.E.ADD.F32.128 (one op for 4 floats)
    if (lane == 0) atomicAdd(&g_deg[d], 1.0f);
}

// ---------------------------------------------------------------------------
// Kernel 3: fused output  out = relu(x@Ws + (sum/max(deg,1))@Wn + b)
// Block = 256 threads: 16 rows x 16 col-groups (4 cols each).
// ---------------------------------------------------------------------------
__global__ __launch_bounds__(256) void out_kernel(const float* __restrict__ x,
                                                  const float* __restrict__ Ws,
                                                  const float* __restrict__ Wn,
                                                  const float* __restrict__ b,
                                                  float* __restrict__ out,
                                                  int n_rows) {
    __shared__ float4 sWs[FEATS * 16];   // [k][jgroup] 16 KB
    __shared__ float4 sWn[FEATS * 16];   // 16 KB
    __shared__ float  sb[FEATS];
    __shared__ float  sx[16][FEATS];     // 4 KB
    __shared__ float  sn[16][FEATS];     // 4 KB
    __shared__ float  sinv[16];

    int tid = threadIdx.x;

    // Stage both weight matrices (row-major [k][j] -> float4 over j)
    {
        const float4* gWs = reinterpret_cast<const float4*>(Ws);
        const float4* gWn = reinterpret_cast<const float4*>(Wn);
        #pragma unroll
        for (int i = 0; i < 4; i++) {
            sWs[tid + 256 * i] = gWs[tid + 256 * i];
            sWn[tid + 256 * i] = gWn[tid + 256 * i];
        }
        if (tid < FEATS) sb[tid] = b[tid];
    }

    int jg   = tid & 15;   // col group: cols 4*jg .. 4*jg+3
    int rloc = tid >> 4;   // local row 0..15

    int row0 = blockIdx.x * 16;
    {
        // Stage 16 rows of x and raw neighbor sums
        int sr = tid >> 4;          // row this thread helps stage
        int sc = tid & 15;          // float4 column
        int grow = row0 + sr;
        if (grow < n_rows) {
            const float4* xr = reinterpret_cast<const float4*>(x + (size_t)grow * FEATS);
            const float4* nr = reinterpret_cast<const float4*>(g_sum + (size_t)grow * FEATS);
            reinterpret_cast<float4*>(&sx[sr][0])[sc] = __ldg(&xr[sc]);
            reinterpret_cast<float4*>(&sn[sr][0])[sc] = nr[sc];
        }
        if (tid < 16) {
            int gr = row0 + tid;
            float dg = (gr < n_rows) ? g_deg[gr] : 1.0f;
            sinv[tid] = 1.0f / fmaxf(dg, 1.0f);
        }
        __syncthreads();

        int row = row0 + rloc;
        if (row < n_rows) {
            float4 accx = make_float4(0.f, 0.f, 0.f, 0.f);
            float4 accn = make_float4(0.f, 0.f, 0.f, 0.f);
            #pragma unroll
            for (int k = 0; k < FEATS; k++) {
                float xv = sx[rloc][k];
                float nv = sn[rloc][k];
                float4 ws = sWs[k * 16 + jg];
                float4 wn = sWn[k * 16 + jg];
                accx.x += xv * ws.x;  accx.y += xv * ws.y;
                accx.z += xv * ws.z;  accx.w += xv * ws.w;
                accn.x += nv * wn.x;  accn.y += nv * wn.y;
                accn.z += nv * wn.z;  accn.w += nv * wn.w;
            }
            float inv = sinv[rloc];
            float4 bb = reinterpret_cast<const float4*>(sb)[jg];
            float4 r;
            r.x = fmaxf(accx.x + inv * accn.x + bb.x, 0.f);
            r.y = fmaxf(accx.y + inv * accn.y + bb.y, 0.f);
            r.z = fmaxf(accx.z + inv * accn.z + bb.z, 0.f);
            r.w = fmaxf(accx.w + inv * accn.w + bb.w, 0.f);
            reinterpret_cast<float4*>(out + (size_t)row * FEATS)[jg] = r;
        }
    }
}

// ---------------------------------------------------------------------------
// Launch
// Inputs (metadata order): x[100000*64] f32, W_self[64*64] f32, W_neigh[64*64] f32,
//                          b[64] f32, src[1e6] i32, dst[1e6] i32, num_dst (scalar)
// ---------------------------------------------------------------------------
extern "C" void kernel_launch(void* const* d_in, const int* in_sizes, int n_in,
                              void* d_out, int out_size) {
    const float* x  = (const float*)d_in[0];
    const float* Ws = (const float*)d_in[1];
    const float* Wn = (const float*)d_in[2];
    const float* b  = (const float*)d_in[3];
    const int*   src = (const int*)d_in[4];
    const int*   dst = (const int*)d_in[5];
    float* out = (float*)d_out;

    int n_edges = in_sizes[4];
    int n_rows  = out_size / FEATS;        // num_dst
    if (n_rows > MAX_NODES) n_rows = MAX_NODES;

    // 1) zero accumulators
    zero_kernel<<<1184, 256>>>(n_rows);

    // 2) scatter: 16 threads/edge
    {
        int threads_total = n_edges * 16;
        int blocks = (threads_total + 255) / 256;
        scatter_kernel<<<blocks, 256>>>(x, src, dst, n_edges);
    }

    // 3) fused GEMM + mean + bias + relu
    {
        int blocks = (n_rows + 15) / 16;
        out_kernel<<<blocks, 256>>>(x, Ws, Wn, b, out, n_rows);
    }
}

// round 3
// speedup vs baseline: 1.3422x; 1.3422x over previous
#include <cuda_runtime.h>
#include <cuda_bf16.h>

#define FEATS 64
#define MAX_NODES 100000

// Scratch (alloc-free rule: __device__ globals)
__device__ float g_sum[(size_t)MAX_NODES * FEATS];
__device__ float g_deg[MAX_NODES];

// ---------------------------------------------------------------------------
// Kernel 1: zero the accumulators
// ---------------------------------------------------------------------------
__global__ void zero_kernel(int n_nodes) {
    int stride = gridDim.x * blockDim.x;
    int i = blockIdx.x * blockDim.x + threadIdx.x;
    int total4 = n_nodes * (FEATS / 4);
    float4 z = make_float4(0.f, 0.f, 0.f, 0.f);
    float4* s4 = reinterpret_cast<float4*>(g_sum);
    for (int idx = i; idx < total4; idx += stride) s4[idx] = z;
    for (int idx = i; idx < n_nodes; idx += stride) g_deg[idx] = 0.f;
}

// ---------------------------------------------------------------------------
// Kernel 2: edge scatter. 16 lanes per edge; float4 vector atomics (RED.128).
// (identical to the round-1 version that passed)
// ---------------------------------------------------------------------------
__global__ void scatter_kernel(const float* __restrict__ x,
                               const int* __restrict__ src,
                               const int* __restrict__ dst,
                               int n_edges) {
    int e    = blockIdx.x * (blockDim.x >> 4) + (threadIdx.x >> 4);
    int lane = threadIdx.x & 15;
    if (e >= n_edges) return;
    int s = __ldg(&src[e]);
    int d = __ldg(&dst[e]);
    const float4* xrow = reinterpret_cast<const float4*>(x + (size_t)s * FEATS);
    float4 v = __ldg(&xrow[lane]);
    float4* srow = reinterpret_cast<float4*>(g_sum + (size_t)d * FEATS);
    atomicAdd(&srow[lane], v);
    if (lane == 0) atomicAdd(&g_deg[d], 1.0f);
}

// ---------------------------------------------------------------------------
// Kernel 3: fused output  out = relu(x@Ws + (sum/max(deg,1))@Wn + b)
// 32-row M-tile, 256 threads = (ty 0..15 -> 2 rows) x (tx 0..15 -> 4 cols).
// Two phases sharing one A buffer: phase 1 = x@Ws, phase 2 = (sum*inv)@Wn.
// Static smem: 32768 (weights) + 8704 (sA) + 256 + 128 = 41856 B  (< 48 KB)
// ---------------------------------------------------------------------------
__global__ __launch_bounds__(256) void out_kernel(const float* __restrict__ x,
                                                  const float* __restrict__ Ws,
                                                  const float* __restrict__ Wn,
                                                  const float* __restrict__ b,
                                                  float* __restrict__ out,
                                                  int n_rows) {
    __shared__ float4 sWs[FEATS][16];    // 16 KB  [k][jgroup]
    __shared__ float4 sWn[FEATS][16];    // 16 KB
    __shared__ float  sA[32][68];        // 8.7 KB (pad 68 -> warp rows hit distinct banks)
    __shared__ float  sb[FEATS];
    __shared__ float  sinv[32];

    int tid  = threadIdx.x;
    int row0 = blockIdx.x * 32;

    // Stage weights (coalesced float4)
    {
        const float4* gWs = reinterpret_cast<const float4*>(Ws);
        const float4* gWn = reinterpret_cast<const float4*>(Wn);
        #pragma unroll
        for (int i = 0; i < 4; i++) {
            int idx = tid + 256 * i;             // 0..1023
            reinterpret_cast<float4*>(sWs)[idx] = __ldg(&gWs[idx]);
            reinterpret_cast<float4*>(sWn)[idx] = __ldg(&gWn[idx]);
        }
        if (tid < FEATS) sb[tid] = b[tid];
        if (tid < 32) {
            int r = row0 + tid;
            float dg = (r < n_rows) ? g_deg[r] : 1.0f;
            sinv[tid] = 1.0f / fmaxf(dg, 1.0f);
        }
    }

    // Stage phase-1 A tile: 32 rows x 16 float4 of x
    {
        const float4* gx = reinterpret_cast<const float4*>(x);
        #pragma unroll
        for (int i = 0; i < 2; i++) {
            int idx = tid + 256 * i;             // 0..511
            int r = idx >> 4, c = idx & 15;
            int grow = row0 + r;
            float4 v = make_float4(0.f, 0.f, 0.f, 0.f);
            if (grow < n_rows) v = __ldg(&gx[(size_t)grow * 16 + c]);
            *reinterpret_cast<float4*>(&sA[r][c * 4]) = v;
        }
    }
    __syncthreads();

    int ty = tid >> 4;    // 0..15 -> rows 2*ty, 2*ty+1
    int tx = tid & 15;    // 0..15 -> cols 4*tx .. 4*tx+3
    int ra = 2 * ty, rb = 2 * ty + 1;

    float4 acc0 = make_float4(0.f, 0.f, 0.f, 0.f);
    float4 acc1 = acc0;

    // Phase 1: x @ Ws
    #pragma unroll
    for (int k = 0; k < FEATS; k++) {
        float a0 = sA[ra][k];
        float a1 = sA[rb][k];
        float4 w = sWs[k][tx];
        acc0.x += a0 * w.x; acc0.y += a0 * w.y; acc0.z += a0 * w.z; acc0.w += a0 * w.w;
        acc1.x += a1 * w.x; acc1.y += a1 * w.y; acc1.z += a1 * w.z; acc1.w += a1 * w.w;
    }
    __syncthreads();

    // Restage A tile with mean-scaled neighbor sums
    {
        const float4* gs = reinterpret_cast<const float4*>(g_sum);
        #pragma unroll
        for (int i = 0; i < 2; i++) {
            int idx = tid + 256 * i;
            int r = idx >> 4, c = idx & 15;
            int grow = row0 + r;
            float4 v = make_float4(0.f, 0.f, 0.f, 0.f);
            if (grow < n_rows) {
                v = gs[(size_t)grow * 16 + c];
                float inv = sinv[r];
                v.x *= inv; v.y *= inv; v.z *= inv; v.w *= inv;
            }
            *reinterpret_cast<float4*>(&sA[r][c * 4]) = v;
        }
    }
    __syncthreads();

    // Phase 2: h_neigh @ Wn (accumulate)
    #pragma unroll
    for (int k = 0; k < FEATS; k++) {
        float a0 = sA[ra][k];
        float a1 = sA[rb][k];
        float4 w = sWn[k][tx];
        acc0.x += a0 * w.x; acc0.y += a0 * w.y; acc0.z += a0 * w.z; acc0.w += a0 * w.w;
        acc1.x += a1 * w.x; acc1.y += a1 * w.y; acc1.z += a1 * w.z; acc1.w += a1 * w.w;
    }

    // Epilogue: + b, relu, store
    float4 bb = reinterpret_cast<const float4*>(sb)[tx];
    float4* out4 = reinterpret_cast<float4*>(out);
    int r0g = row0 + ra;
    if (r0g < n_rows) {
        float4 r;
        r.x = fmaxf(acc0.x + bb.x, 0.f);
        r.y = fmaxf(acc0.y + bb.y, 0.f);
        r.z = fmaxf(acc0.z + bb.z, 0.f);
        r.w = fmaxf(acc0.w + bb.w, 0.f);
        out4[(size_t)r0g * 16 + tx] = r;
    }
    int r1g = row0 + rb;
    if (r1g < n_rows) {
        float4 r;
        r.x = fmaxf(acc1.x + bb.x, 0.f);
        r.y = fmaxf(acc1.y + bb.y, 0.f);
        r.z = fmaxf(acc1.z + bb.z, 0.f);
        r.w = fmaxf(acc1.w + bb.w, 0.f);
        out4[(size_t)r1g * 16 + tx] = r;
    }
}

// ---------------------------------------------------------------------------
// Launch. Inputs: x f32[100000,64], W_self f32[64,64], W_neigh f32[64,64],
//                 b f32[64], src i32[1e6], dst i32[1e6], num_dst scalar
// ---------------------------------------------------------------------------
extern "C" void kernel_launch(void* const* d_in, const int* in_sizes, int n_in,
                              void* d_out, int out_size) {
    const float* x   = (const float*)d_in[0];
    const float* Ws  = (const float*)d_in[1];
    const float* Wn  = (const float*)d_in[2];
    const float* b   = (const float*)d_in[3];
    const int*   src = (const int*)d_in[4];
    const int*   dst = (const int*)d_in[5];
    float* out = (float*)d_out;

    int n_edges = in_sizes[4];
    int n_rows  = out_size / FEATS;
    if (n_rows > MAX_NODES) n_rows = MAX_NODES;

    // 1) zero accumulators
    zero_kernel<<<1184, 256>>>(n_rows);

    // 2) scatter: 16 threads/edge, float4 atomics
    {
        long long threads_total = (long long)n_edges * 16;
        int blocks = (int)((threads_total + 255) / 256);
        scatter_kernel<<<blocks, 256>>>(x, src, dst, n_edges);
    }

    // 3) fused GEMM + mean + bias + relu
    {
        int blocks = (n_rows + 31) / 32;
        out_kernel<<<blocks, 256>>>(x, Ws, Wn, b, out, n_rows);
    }
}

// round 4
// speedup vs baseline: 1.3641x; 1.0163x over previous
#include <cuda_runtime.h>
#include <cuda_bf16.h>

#define FEATS 64
#define MAX_NODES 100000

// Scratch (alloc-free rule: __device__ globals)
__device__ float g_sum[(size_t)MAX_NODES * FEATS];
__device__ float g_deg[MAX_NODES];

// ---------------------------------------------------------------------------
// packed f32x2 FMA (sm_103a FFMA2) — 2 MACs per issue slot
// ---------------------------------------------------------------------------
__device__ __forceinline__ unsigned long long fma2(unsigned long long a,
                                                   unsigned long long b,
                                                   unsigned long long c) {
    unsigned long long d;
    asm("fma.rn.f32x2 %0, %1, %2, %3;" : "=l"(d) : "l"(a), "l"(b), "l"(c));
    return d;
}

// ---------------------------------------------------------------------------
// Kernel 1: zero the accumulators
// ---------------------------------------------------------------------------
__global__ void zero_kernel(int n_nodes) {
    int stride = gridDim.x * blockDim.x;
    int i = blockIdx.x * blockDim.x + threadIdx.x;
    int total4 = n_nodes * (FEATS / 4);
    float4 z = make_float4(0.f, 0.f, 0.f, 0.f);
    float4* s4 = reinterpret_cast<float4*>(g_sum);
    for (int idx = i; idx < total4; idx += stride) s4[idx] = z;
    for (int idx = i; idx < n_nodes; idx += stride) g_deg[idx] = 0.f;
}

// ---------------------------------------------------------------------------
// Kernel 2: edge scatter. 16 lanes per edge; float4 vector atomics (RED.128).
// (unchanged from the passing version)
// ---------------------------------------------------------------------------
__global__ void scatter_kernel(const float* __restrict__ x,
                               const int* __restrict__ src,
                               const int* __restrict__ dst,
                               int n_edges) {
    int e    = blockIdx.x * (blockDim.x >> 4) + (threadIdx.x >> 4);
    int lane = threadIdx.x & 15;
    if (e >= n_edges) return;
    int s = __ldg(&src[e]);
    int d = __ldg(&dst[e]);
    const float4* xrow = reinterpret_cast<const float4*>(x + (size_t)s * FEATS);
    float4 v = __ldg(&xrow[lane]);
    float4* srow = reinterpret_cast<float4*>(g_sum + (size_t)d * FEATS);
    atomicAdd(&srow[lane], v);
    if (lane == 0) atomicAdd(&g_deg[d], 1.0f);
}

// ---------------------------------------------------------------------------
// Kernel 3: out = relu(x@Ws + (sum/max(deg,1))@Wn + b)
// 64-row M-tile, 256 threads: ty(16) -> 4 rows, tx(16) -> 4 cols.
// A staged DUPLICATED as float2 (a,a); inner loop = 5 LDS + 8 FFMA2 per k.
// Two phases reuse the A buffer (x then scaled neighbor sums).
// Dynamic smem: sA2 64x65 f2 (33280) + sWs/sWn 16K each + sb/sinv (512) = 66560 B
// ---------------------------------------------------------------------------
#define SA2_STRIDE 65
#define SMEM_A_BYTES (64 * SA2_STRIDE * 8)                 // 33280
#define SMEM_TOTAL (SMEM_A_BYTES + 2 * 16384 + 512)        // 66560

__global__ __launch_bounds__(256) void out_kernel(const float* __restrict__ x,
                                                  const float* __restrict__ Ws,
                                                  const float* __restrict__ Wn,
                                                  const float* __restrict__ b,
                                                  float* __restrict__ out,
                                                  int n_rows) {
    extern __shared__ char smem[];
    float2* sA2 = reinterpret_cast<float2*>(smem);                        // [64][65]
    float4* sWs = reinterpret_cast<float4*>(smem + SMEM_A_BYTES);         // [64][16]
    float4* sWn = reinterpret_cast<float4*>(smem + SMEM_A_BYTES + 16384); // [64][16]
    float*  sb   = reinterpret_cast<float*>(smem + SMEM_A_BYTES + 32768); // [64]
    float*  sinv = sb + 64;                                                // [64]

    int tid  = threadIdx.x;
    int row0 = blockIdx.x * 64;

    // Stage weights (coalesced float4)
    {
        const float4* gWs = reinterpret_cast<const float4*>(Ws);
        const float4* gWn = reinterpret_cast<const float4*>(Wn);
        #pragma unroll
        for (int i = 0; i < 4; i++) {
            int idx = tid + 256 * i;             // 0..1023
            sWs[idx] = __ldg(&gWs[idx]);
            sWn[idx] = __ldg(&gWn[idx]);
        }
        if (tid < FEATS) sb[tid] = b[tid];
        if (tid < 64) {
            int r = row0 + tid;
            float dg = (r < n_rows) ? g_deg[r] : 1.0f;
            sinv[tid] = 1.0f / fmaxf(dg, 1.0f);
        }
    }

    // Stage phase-1 A tile: 64 rows x 16 float4 of x, duplicated to float2 pairs
    {
        const float4* gx = reinterpret_cast<const float4*>(x);
        #pragma unroll
        for (int i = 0; i < 4; i++) {
            int idx = tid + 256 * i;             // 0..1023
            int r = idx >> 4, c = idx & 15;
            int grow = row0 + r;
            float4 v = make_float4(0.f, 0.f, 0.f, 0.f);
            if (grow < n_rows) v = __ldg(&gx[(size_t)grow * 16 + c]);
            float2* dstp = &sA2[r * SA2_STRIDE + c * 4];
            dstp[0] = make_float2(v.x, v.x);
            dstp[1] = make_float2(v.y, v.y);
            dstp[2] = make_float2(v.z, v.z);
            dstp[3] = make_float2(v.w, v.w);
        }
    }
    __syncthreads();

    int ty = tid >> 4;        // 0..15 -> rows ty*4 .. ty*4+3
    int tx = tid & 15;        // 0..15 -> cols tx*4 .. tx*4+3

    unsigned long long acc[4][2];
    #pragma unroll
    for (int r = 0; r < 4; r++) { acc[r][0] = 0ull; acc[r][1] = 0ull; }

    const unsigned long long* a0p =
        reinterpret_cast<const unsigned long long*>(&sA2[(ty * 4 + 0) * SA2_STRIDE]);
    const unsigned long long* a1p = a0p + SA2_STRIDE;
    const unsigned long long* a2p = a1p + SA2_STRIDE;
    const unsigned long long* a3p = a2p + SA2_STRIDE;

    // Phase 1: x @ Ws
    #pragma unroll 16
    for (int k = 0; k < FEATS; k++) {
        ulonglong2 w = *reinterpret_cast<const ulonglong2*>(&sWs[k * 16 + tx]);
        unsigned long long a0 = a0p[k], a1 = a1p[k], a2 = a2p[k], a3 = a3p[k];
        acc[0][0] = fma2(a0, w.x, acc[0][0]);  acc[0][1] = fma2(a0, w.y, acc[0][1]);
        acc[1][0] = fma2(a1, w.x, acc[1][0]);  acc[1][1] = fma2(a1, w.y, acc[1][1]);
        acc[2][0] = fma2(a2, w.x, acc[2][0]);  acc[2][1] = fma2(a2, w.y, acc[2][1]);
        acc[3][0] = fma2(a3, w.x, acc[3][0]);  acc[3][1] = fma2(a3, w.y, acc[3][1]);
    }
    __syncthreads();

    // Restage A with mean-scaled neighbor sums (duplicated)
    {
        const float4* gs = reinterpret_cast<const float4*>(g_sum);
        #pragma unroll
        for (int i = 0; i < 4; i++) {
            int idx = tid + 256 * i;
            int r = idx >> 4, c = idx & 15;
            int grow = row0 + r;
            float4 v = make_float4(0.f, 0.f, 0.f, 0.f);
            if (grow < n_rows) {
                v = gs[(size_t)grow * 16 + c];
                float inv = sinv[r];
                v.x *= inv; v.y *= inv; v.z *= inv; v.w *= inv;
            }
            float2* dstp = &sA2[r * SA2_STRIDE + c * 4];
            dstp[0] = make_float2(v.x, v.x);
            dstp[1] = make_float2(v.y, v.y);
            dstp[2] = make_float2(v.z, v.z);
            dstp[3] = make_float2(v.w, v.w);
        }
    }
    __syncthreads();

    // Phase 2: h_neigh @ Wn (accumulate)
    #pragma unroll 16
    for (int k = 0; k < FEATS; k++) {
        ulonglong2 w = *reinterpret_cast<const ulonglong2*>(&sWn[k * 16 + tx]);
        unsigned long long a0 = a0p[k], a1 = a1p[k], a2 = a2p[k], a3 = a3p[k];
        acc[0][0] = fma2(a0, w.x, acc[0][0]);  acc[0][1] = fma2(a0, w.y, acc[0][1]);
        acc[1][0] = fma2(a1, w.x, acc[1][0]);  acc[1][1] = fma2(a1, w.y, acc[1][1]);
        acc[2][0] = fma2(a2, w.x, acc[2][0]);  acc[2][1] = fma2(a2, w.y, acc[2][1]);
        acc[3][0] = fma2(a3, w.x, acc[3][0]);  acc[3][1] = fma2(a3, w.y, acc[3][1]);
    }

    // Epilogue: + b, relu, store
    float4 bb = reinterpret_cast<const float4*>(sb)[tx];
    float4* out4 = reinterpret_cast<float4*>(out);
    #pragma unroll
    for (int r = 0; r < 4; r++) {
        int row = row0 + ty * 4 + r;
        if (row < n_rows) {
            float2 p01 = *reinterpret_cast<float2*>(&acc[r][0]);
            float2 p23 = *reinterpret_cast<float2*>(&acc[r][1]);
            float4 o;
            o.x = fmaxf(p01.x + bb.x, 0.f);
            o.y = fmaxf(p01.y + bb.y, 0.f);
            o.z = fmaxf(p23.x + bb.z, 0.f);
            o.w = fmaxf(p23.y + bb.w, 0.f);
            out4[(size_t)row * 16 + tx] = o;
        }
    }
}

// ---------------------------------------------------------------------------
// Launch. Inputs: x f32[100000,64], W_self f32[64,64], W_neigh f32[64,64],
//                 b f32[64], src i32[1e6], dst i32[1e6], num_dst scalar
// ---------------------------------------------------------------------------
extern "C" void kernel_launch(void* const* d_in, const int* in_sizes, int n_in,
                              void* d_out, int out_size) {
    const float* x   = (const float*)d_in[0];
    const float* Ws  = (const float*)d_in[1];
    const float* Wn  = (const float*)d_in[2];
    const float* b   = (const float*)d_in[3];
    const int*   src = (const int*)d_in[4];
    const int*   dst = (const int*)d_in[5];
    float* out = (float*)d_out;

    int n_edges = in_sizes[4];
    int n_rows  = out_size / FEATS;
    if (n_rows > MAX_NODES) n_rows = MAX_NODES;

    // 1) zero accumulators
    zero_kernel<<<1184, 256>>>(n_rows);

    // 2) scatter: 16 threads/edge, float4 atomics
    {
        long long threads_total = (long long)n_edges * 16;
        int blocks = (int)((threads_total + 255) / 256);
        scatter_kernel<<<blocks, 256>>>(x, src, dst, n_edges);
    }

    // 3) fused GEMM + mean + bias + relu (66.5 KB dynamic smem)
    {
        static int smem_set = 0;
        if (!smem_set) {
            cudaFuncSetAttribute(out_kernel,
                                 cudaFuncAttributeMaxDynamicSharedMemorySize,
                                 SMEM_TOTAL);
            smem_set = 1;
        }
        int blocks = (n_rows + 63) / 64;
        out_kernel<<<blocks, 256, SMEM_TOTAL>>>(x, Ws, Wn, b, out, n_rows);
    }
}